// round 8
// baseline (speedup 1.0000x reference)
#include <cuda_runtime.h>
#include <cstdint>

#define NN 50000
#define EE 800000
#define D  128
#define DE 16
#define NSB 49           // scan blocks: ceil(50000/1024)
#define CHUNK 64         // edges per warp in segmented aggregation
#define NCHUNK (EE / CHUNK)   // 12500, exact

#define NODE_SMEM (2*D*D*4 + 4*D*4)

// Scratch (static __device__ arrays: no allocation allowed)
__device__ float g_h[2][NN * D];
__device__ float g_S[NN * D];
__device__ float g_Z[NN * D];
__device__ int   g_deg[NN];
__device__ float g_gn[NN];
__device__ int   g_off[NN + 1];
__device__ int   g_cur[NN];
__device__ int   g_pre[NN];                 // block-local exclusive prefix
__device__ int   g_bsum[64];                // per-block sums -> exclusive prefix
__device__ int4  g_prw[EE];                 // {row, bitcast(w), dst, 0} dest-sorted
__device__ float g_eas[(size_t)EE * DE];    // edge_attr in dest-sorted order

#define PACK2(d, x)      asm("mov.b64 %0, {%1, %1};" : "=l"(d) : "f"(x))
#define FMA2(d, a, b, c) asm("fma.rn.f32x2 %0, %1, %2, %3;" : "=l"(d) : "l"(a), "l"(b), "l"(c))

__global__ void k_zero_deg() {
    int i = blockIdx.x * blockDim.x + threadIdx.x;
    if (i < NN) g_deg[i] = 0;
}

__global__ void k_zero_sz() {
    int i = blockIdx.x * blockDim.x + threadIdx.x;
    if (i < NN * D / 4) {
        ((float4*)g_S)[i] = make_float4(0.f, 0.f, 0.f, 0.f);
        ((float4*)g_Z)[i] = make_float4(0.f, 0.f, 0.f, 0.f);
    }
}

__global__ void k_deg(const int* __restrict__ col) {
    int e = blockIdx.x * blockDim.x + threadIdx.x;
    if (e < EE) atomicAdd(&g_deg[col[e]], 1);
}

// Pass 1: block-local exclusive scan of g_deg; write local prefix + block sum.
__global__ __launch_bounds__(1024) void k_scan1() {
    __shared__ int sw[32];
    const int t = threadIdx.x, lane = t & 31, wid = t >> 5;
    const int i = blockIdx.x * 1024 + t;
    const int v = (i < NN) ? g_deg[i] : 0;
    int x = v;
#pragma unroll
    for (int o = 1; o < 32; o <<= 1) {
        int y = __shfl_up_sync(0xffffffffu, x, o);
        if (lane >= o) x += y;
    }
    if (lane == 31) sw[wid] = x;
    __syncthreads();
    if (wid == 0) {
        int s = sw[lane];
#pragma unroll
        for (int o = 1; o < 32; o <<= 1) {
            int y = __shfl_up_sync(0xffffffffu, s, o);
            if (lane >= o) s += y;
        }
        sw[lane] = s;
    }
    __syncthreads();
    const int pre = (wid ? sw[wid - 1] : 0) + x - v;  // exclusive within block
    if (i < NN) g_pre[i] = pre;
    if (t == 1023) g_bsum[blockIdx.x] = pre + v;
}

// Pass 2: one warp scans the 49 block sums (exclusive).
__global__ void k_scan2() {
    const int lane = threadIdx.x;
    if (lane >= 32) return;
    int a = 0, b = 0;
    if (lane < NSB) a = g_bsum[lane];
    if (lane + 32 < NSB) b = g_bsum[lane + 32];
    const int a0 = a, b0 = b;
#pragma unroll
    for (int o = 1; o < 32; o <<= 1) {
        int y = __shfl_up_sync(0xffffffffu, a, o);
        if (lane >= o) a += y;
    }
    const int totA = __shfl_sync(0xffffffffu, a, 31);
#pragma unroll
    for (int o = 1; o < 32; o <<= 1) {
        int y = __shfl_up_sync(0xffffffffu, b, o);
        if (lane >= o) b += y;
    }
    if (lane < NSB) g_bsum[lane] = a - a0;
    if (lane + 32 < NSB) g_bsum[lane + 32] = totA + b - b0;
}

// Pass 3: finalize offsets, cursors, gcn-norm factors.
__global__ __launch_bounds__(1024) void k_fin() {
    const int i = blockIdx.x * 1024 + threadIdx.x;
    if (i < NN) {
        const int o = g_pre[i] + g_bsum[blockIdx.x];
        g_off[i] = o;
        g_cur[i] = o;
        const int d = g_deg[i];
        g_gn[i] = (d > 0) ? rsqrtf((float)d) : 0.f;
    }
    if (i == 0) g_off[NN] = EE;
}

// Counting-sort permute: edge e -> slot pos (sorted by destination col).
__global__ void k_perm(const int* __restrict__ row, const int* __restrict__ col,
                       const float* __restrict__ eattr) {
    int e = blockIdx.x * blockDim.x + threadIdx.x;
    if (e >= EE) return;
    const int c = col[e];
    const int r = row[e];
    const int pos = atomicAdd(&g_cur[c], 1);
    g_prw[pos] = make_int4(r, __float_as_int(g_gn[r] * g_gn[c]), c, 0);
    const float4* src = (const float4*)(eattr + (size_t)e * DE);
    float4* dst = (float4*)(g_eas + (size_t)pos * DE);
    dst[0] = src[0]; dst[1] = src[1]; dst[2] = src[2]; dst[3] = src[3];
}

// Segmented aggregation: one warp per CHUNK consecutive (dest-sorted) edges.
// Perfectly load-balanced; segment partials flushed with red.global.add.v4
// (S/Z pre-zeroed). dst is warp-uniform -> uniform flush branch.
__global__ __launch_bounds__(256, 2) void k_agg(
    const float* __restrict__ x,
    const float* __restrict__ w1,
    const float* __restrict__ b1,
    int layer)
{
    const float* __restrict__ h = (layer == 0) ? x : g_h[(layer - 1) & 1];
    const int lane = threadIdx.x & 31;

    // W1 columns for this lane in registers as f32x2 pairs
    unsigned long long w101[DE], w123[DE], b101, b123;
    {
        const ulonglong2 bv = *(const ulonglong2*)(b1 + lane * 4);
        b101 = bv.x; b123 = bv.y;
#pragma unroll
        for (int k = 0; k < DE; ++k) {
            const ulonglong2 wv = *(const ulonglong2*)(w1 + k * D + lane * 4);
            w101[k] = wv.x; w123[k] = wv.y;
        }
    }

    const int warp = (blockIdx.x * blockDim.x + threadIdx.x) >> 5;
    if (warp >= NCHUNK) return;
    const int e0 = warp * CHUNK;
    const int e1 = e0 + CHUNK;

    unsigned long long s01 = 0ull, s23 = 0ull;
    float az0 = 0.f, az1 = 0.f, az2 = 0.f, az3 = 0.f;

    int4 rw = __ldg(g_prw + e0);
    float a = (lane < DE) ? __ldg(g_eas + (size_t)e0 * DE + lane) : 0.f;
    int cur_dst = rw.z;

    for (int e = e0; e < e1; ++e) {
        const int4 cur = rw;
        const float ac = a;

        // issue the h gather early; consumed at the end of the body
        const ulonglong2 hv = __ldg((const ulonglong2*)(h + (size_t)cur.x * D + lane * 4));

        // prefetch next edge (sequential -> mostly L1 line hits)
        if (e + 1 < e1) {
            rw = __ldg(g_prw + e + 1);
            a = (lane < DE) ? __ldg(g_eas + (size_t)(e + 1) * DE + lane) : 0.f;
        }

        // segment boundary? (uniform branch)
        if (cur.z != cur_dst) {
            float* sp = g_S + (size_t)cur_dst * D + lane * 4;
            float* zp = g_Z + (size_t)cur_dst * D + lane * 4;
            const float2 sl = *(const float2*)&s01;
            const float2 sh = *(const float2*)&s23;
            asm volatile("red.global.add.v4.f32 [%0], {%1,%2,%3,%4};"
                         :: "l"(sp), "f"(sl.x), "f"(sl.y), "f"(sh.x), "f"(sh.y) : "memory");
            asm volatile("red.global.add.v4.f32 [%0], {%1,%2,%3,%4};"
                         :: "l"(zp), "f"(az0), "f"(az1), "f"(az2), "f"(az3) : "memory");
            s01 = 0ull; s23 = 0ull;
            az0 = az1 = az2 = az3 = 0.f;
            cur_dst = cur.z;
        }

        // edge MLP: z = ea @ W1 + b1 (f32x2)
        unsigned long long z01 = b101, z23 = b123;
#pragma unroll
        for (int k = 0; k < DE; ++k) {
            const float ak = __shfl_sync(0xffffffffu, ac, k);
            unsigned long long ak2; PACK2(ak2, ak);
            FMA2(z01, ak2, w101[k], z01);
            FMA2(z23, ak2, w123[k], z23);
        }
        const float2 zl = *(const float2*)&z01;
        const float2 zh = *(const float2*)&z23;
        az0 += fmaxf(zl.x, 0.f); az1 += fmaxf(zl.y, 0.f);
        az2 += fmaxf(zh.x, 0.f); az3 += fmaxf(zh.y, 0.f);

        unsigned long long wp; PACK2(wp, __int_as_float(cur.y));
        FMA2(s01, wp, hv.x, s01);
        FMA2(s23, wp, hv.y, s23);
    }

    // final flush
    {
        float* sp = g_S + (size_t)cur_dst * D + lane * 4;
        float* zp = g_Z + (size_t)cur_dst * D + lane * 4;
        const float2 sl = *(const float2*)&s01;
        const float2 sh = *(const float2*)&s23;
        asm volatile("red.global.add.v4.f32 [%0], {%1,%2,%3,%4};"
                     :: "l"(sp), "f"(sl.x), "f"(sl.y), "f"(sh.x), "f"(sh.y) : "memory");
        asm volatile("red.global.add.v4.f32 [%0], {%1,%2,%3,%4};"
                     :: "l"(zp), "f"(az0), "f"(az1), "f"(az2), "f"(az3) : "memory");
    }
}

// Fused: out = S @ lin_w + Z @ W2 + deg*b2 + bias ; LayerNorm ; relu  (f32x2 GEMM)
// Also zeroes S/Z rows for the NEXT layer's segmented aggregation (layers 0,1).
__global__ __launch_bounds__(512, 1) void k_node(
    const float* __restrict__ lw,
    const float* __restrict__ w2,
    const float* __restrict__ b2,
    const float* __restrict__ bias,
    const float* __restrict__ lnw,
    const float* __restrict__ lnb,
    float* __restrict__ dout,
    int layer)
{
    extern __shared__ __align__(16) float sm[];
    float* s_lw  = sm;
    float* s_w2  = sm + D * D;
    float* s_vec = sm + 2 * D * D;   // [b2 | bias | lnw | lnb]

    for (int i = threadIdx.x; i < D * D / 4; i += 512) {
        ((float4*)s_lw)[i] = ((const float4*)lw)[i];
        ((float4*)s_w2)[i] = ((const float4*)w2)[i];
    }
    if (threadIdx.x < D) {
        s_vec[threadIdx.x]         = b2[threadIdx.x];
        s_vec[D     + threadIdx.x] = bias[threadIdx.x];
        s_vec[2 * D + threadIdx.x] = lnw[threadIdx.x];
        s_vec[3 * D + threadIdx.x] = lnb[threadIdx.x];
    }
    __syncthreads();

    float* hout = (layer == 2) ? dout : g_h[layer & 1];
    const int lane = threadIdx.x & 31;
    const int wid  = threadIdx.x >> 5;
    const ulonglong2* lw2 = (const ulonglong2*)s_lw;
    const ulonglong2* w22 = (const ulonglong2*)s_w2;

    for (int tile = blockIdx.x * 64; tile < NN; tile += gridDim.x * 64) {
        const int r0 = tile + wid * 4;
        unsigned long long acc01[4], acc23[4];
#pragma unroll
        for (int i = 0; i < 4; ++i) { acc01[i] = 0ull; acc23[i] = 0ull; }

#pragma unroll 2
        for (int k = 0; k < D; k += 4) {
            float4 sv[4], zv[4];
#pragma unroll
            for (int i = 0; i < 4; ++i) {
                const int r = r0 + i;
                if (r < NN) {
                    sv[i] = __ldg((const float4*)(g_S + (size_t)r * D + k));
                    zv[i] = __ldg((const float4*)(g_Z + (size_t)r * D + k));
                } else {
                    sv[i] = make_float4(0.f, 0.f, 0.f, 0.f);
                    zv[i] = make_float4(0.f, 0.f, 0.f, 0.f);
                }
            }
#pragma unroll
            for (int kk = 0; kk < 4; ++kk) {
                const ulonglong2 wl = lw2[(k + kk) * 32 + lane];
                const ulonglong2 wv = w22[(k + kk) * 32 + lane];
#pragma unroll
                for (int i = 0; i < 4; ++i) {
                    const float sx = ((const float*)&sv[i])[kk];
                    const float zx = ((const float*)&zv[i])[kk];
                    unsigned long long sx2, zx2;
                    PACK2(sx2, sx);
                    PACK2(zx2, zx);
                    FMA2(acc01[i], sx2, wl.x, acc01[i]);
                    FMA2(acc01[i], zx2, wv.x, acc01[i]);
                    FMA2(acc23[i], sx2, wl.y, acc23[i]);
                    FMA2(acc23[i], zx2, wv.y, acc23[i]);
                }
            }
        }

        // Epilogue: +deg*b2 +bias, LayerNorm, relu, store; zero S/Z for next layer
#pragma unroll
        for (int i = 0; i < 4; ++i) {
            const int r = r0 + i;
            if (r >= NN) continue;
            const float dg = (float)g_deg[r];
            const float2 a01 = *(const float2*)&acc01[i];
            const float2 a23 = *(const float2*)&acc23[i];
            float o[4] = { a01.x, a01.y, a23.x, a23.y };
#pragma unroll
            for (int jj = 0; jj < 4; ++jj) {
                const int c = lane * 4 + jj;
                o[jj] = o[jj] + dg * s_vec[c] + s_vec[D + c];
            }
            float sum = o[0] + o[1] + o[2] + o[3];
#pragma unroll
            for (int off = 16; off > 0; off >>= 1)
                sum += __shfl_xor_sync(0xffffffffu, sum, off);
            const float mu = sum * (1.f / D);
            float sq = 0.f;
#pragma unroll
            for (int jj = 0; jj < 4; ++jj) { const float dd = o[jj] - mu; sq = fmaf(dd, dd, sq); }
#pragma unroll
            for (int off = 16; off > 0; off >>= 1)
                sq += __shfl_xor_sync(0xffffffffu, sq, off);
            const float inv = rsqrtf(sq * (1.f / D) + 1e-5f);

            float4 res;
            float* rp = (float*)&res;
#pragma unroll
            for (int jj = 0; jj < 4; ++jj) {
                const int c = lane * 4 + jj;
                rp[jj] = fmaxf(fmaf((o[jj] - mu) * inv, s_vec[2 * D + c], s_vec[3 * D + c]), 0.f);
            }
            *(float4*)(hout + (size_t)r * D + lane * 4) = res;

            if (layer != 2) {
                const float4 zz = make_float4(0.f, 0.f, 0.f, 0.f);
                *(float4*)(g_S + (size_t)r * D + lane * 4) = zz;
                *(float4*)(g_Z + (size_t)r * D + lane * 4) = zz;
            }
        }
    }
}

extern "C" void kernel_launch(void* const* d_in, const int* in_sizes, int n_in,
                              void* d_out, int out_size)
{
    const float* x     = (const float*)d_in[0];
    const float* eattr = (const float*)d_in[1];
    const float* lin_w = (const float*)d_in[2];
    const float* ew1   = (const float*)d_in[3];
    const float* eb1   = (const float*)d_in[4];
    const float* ew2   = (const float*)d_in[5];
    const float* eb2   = (const float*)d_in[6];
    const float* bias  = (const float*)d_in[7];
    const float* lnw   = (const float*)d_in[8];
    const float* lnb   = (const float*)d_in[9];
    const int*   eidx  = (const int*)d_in[10];
    float* out = (float*)d_out;

    cudaFuncSetAttribute(k_node, cudaFuncAttributeMaxDynamicSharedMemorySize, NODE_SMEM);

    const int* erow = eidx;
    const int* ecol = eidx + EE;

    k_zero_deg<<<(NN + 1023) / 1024, 1024>>>();
    k_zero_sz<<<(NN * D / 4 + 255) / 256, 256>>>();   // layer-0 S/Z zero
    k_deg<<<(EE + 255) / 256, 256>>>(ecol);
    k_scan1<<<NSB, 1024>>>();
    k_scan2<<<1, 32>>>();
    k_fin<<<NSB, 1024>>>();
    k_perm<<<(EE + 255) / 256, 256>>>(erow, ecol, eattr);

    for (int l = 0; l < 3; ++l) {
        k_agg<<<(NCHUNK * 32 + 255) / 256, 256>>>(x, ew1 + l * DE * D, eb1 + l * D, l);
        k_node<<<152, 512, NODE_SMEM>>>(lin_w + l * D * D, ew2 + l * D * D,
                                        eb2 + l * D, bias + l * D,
                                        lnw + l * D, lnb + l * D, out, l);
    }
}

// round 9
// speedup vs baseline: 1.0341x; 1.0341x over previous
#include <cuda_runtime.h>
#include <cstdint>

#define NN 50000
#define EE 800000
#define D  128
#define DE 16
#define NSB 49           // scan blocks: ceil(50000/1024)

#define NODE_SMEM (2*D*D*4 + 4*D*4)

// Scratch (static __device__ arrays: no allocation allowed)
__device__ float g_h[2][NN * D];
__device__ float g_S[NN * D];
__device__ float g_Z[NN * D];
__device__ int   g_deg[NN];
__device__ float g_gn[NN];
__device__ int   g_off[NN + 1];
__device__ int   g_cur[NN];
__device__ int   g_pre[NN];                 // block-local exclusive prefix
__device__ int   g_bsum[64];                // per-block sums -> exclusive prefix
__device__ int2  g_prw[EE];                 // {row, bitcast(w)} dest-sorted
__device__ float g_eas[(size_t)EE * DE];    // edge_attr in dest-sorted order

#define PACK2(d, x)      asm("mov.b64 %0, {%1, %1};" : "=l"(d) : "f"(x))
#define FMA2(d, a, b, c) asm("fma.rn.f32x2 %0, %1, %2, %3;" : "=l"(d) : "l"(a), "l"(b), "l"(c))

__global__ void k_zero_deg() {
    int i = blockIdx.x * blockDim.x + threadIdx.x;
    if (i < NN) g_deg[i] = 0;
}

__global__ void k_deg(const int* __restrict__ col) {
    int e = blockIdx.x * blockDim.x + threadIdx.x;
    if (e < EE) atomicAdd(&g_deg[col[e]], 1);
}

// Pass 1: block-local exclusive scan of g_deg; write local prefix + block sum.
__global__ __launch_bounds__(1024) void k_scan1() {
    __shared__ int sw[32];
    const int t = threadIdx.x, lane = t & 31, wid = t >> 5;
    const int i = blockIdx.x * 1024 + t;
    const int v = (i < NN) ? g_deg[i] : 0;
    int x = v;
#pragma unroll
    for (int o = 1; o < 32; o <<= 1) {
        int y = __shfl_up_sync(0xffffffffu, x, o);
        if (lane >= o) x += y;
    }
    if (lane == 31) sw[wid] = x;
    __syncthreads();
    if (wid == 0) {
        int s = sw[lane];
#pragma unroll
        for (int o = 1; o < 32; o <<= 1) {
            int y = __shfl_up_sync(0xffffffffu, s, o);
            if (lane >= o) s += y;
        }
        sw[lane] = s;
    }
    __syncthreads();
    const int pre = (wid ? sw[wid - 1] : 0) + x - v;  // exclusive within block
    if (i < NN) g_pre[i] = pre;
    if (t == 1023) g_bsum[blockIdx.x] = pre + v;
}

// Pass 2: one warp scans the 49 block sums (exclusive).
__global__ void k_scan2() {
    const int lane = threadIdx.x;
    if (lane >= 32) return;
    int a = 0, b = 0;
    if (lane < NSB) a = g_bsum[lane];
    if (lane + 32 < NSB) b = g_bsum[lane + 32];
    const int a0 = a, b0 = b;
#pragma unroll
    for (int o = 1; o < 32; o <<= 1) {
        int y = __shfl_up_sync(0xffffffffu, a, o);
        if (lane >= o) a += y;
    }
    const int totA = __shfl_sync(0xffffffffu, a, 31);
#pragma unroll
    for (int o = 1; o < 32; o <<= 1) {
        int y = __shfl_up_sync(0xffffffffu, b, o);
        if (lane >= o) b += y;
    }
    if (lane < NSB) g_bsum[lane] = a - a0;
    if (lane + 32 < NSB) g_bsum[lane + 32] = totA + b - b0;
}

// Pass 3: finalize offsets, cursors, gcn-norm factors.
__global__ __launch_bounds__(1024) void k_fin() {
    const int i = blockIdx.x * 1024 + threadIdx.x;
    if (i < NN) {
        const int o = g_pre[i] + g_bsum[blockIdx.x];
        g_off[i] = o;
        g_cur[i] = o;
        const int d = g_deg[i];
        g_gn[i] = (d > 0) ? rsqrtf((float)d) : 0.f;
    }
    if (i == 0) g_off[NN] = EE;
}

// Counting-sort permute: edge e -> slot pos (sorted by destination col).
__global__ void k_perm(const int* __restrict__ row, const int* __restrict__ col,
                       const float* __restrict__ eattr) {
    int e = blockIdx.x * blockDim.x + threadIdx.x;
    if (e >= EE) return;
    const int c = col[e];
    const int r = row[e];
    const int pos = atomicAdd(&g_cur[c], 1);
    g_prw[pos] = make_int2(r, __float_as_int(g_gn[r] * g_gn[c]));
    const float4* src = (const float4*)(eattr + (size_t)e * DE);
    float4* dst = (float4*)(g_eas + (size_t)pos * DE);
    dst[0] = src[0]; dst[1] = src[1]; dst[2] = src[2]; dst[3] = src[3];
}

// One warp per destination node, 2 edges per iteration (two independent MLP
// chains). ea comes in via uniform-address LDG.128 (no shfl). 2-warp blocks
// for fine-grained load balance.
__global__ __launch_bounds__(64) void k_agg(
    const float* __restrict__ x,
    const float* __restrict__ w1,
    const float* __restrict__ b1,
    int layer)
{
    const float* __restrict__ h = (layer == 0) ? x : g_h[(layer - 1) & 1];
    const int lane = threadIdx.x & 31;

    // W1 columns for this lane in registers as f32x2 pairs
    unsigned long long w101[DE], w123[DE], b101, b123;
    {
        const ulonglong2 bv = *(const ulonglong2*)(b1 + lane * 4);
        b101 = bv.x; b123 = bv.y;
#pragma unroll
        for (int k = 0; k < DE; ++k) {
            const ulonglong2 wv = *(const ulonglong2*)(w1 + k * D + lane * 4);
            w101[k] = wv.x; w123[k] = wv.y;
        }
    }

    const int node = blockIdx.x * 2 + (threadIdx.x >> 5);
    if (node >= NN) return;
    const int j0 = g_off[node], j1 = g_off[node + 1];
    const int cnt = j1 - j0;

    unsigned long long s01 = 0ull, s23 = 0ull;
    float az0 = 0.f, az1 = 0.f, az2 = 0.f, az3 = 0.f;

    const int npairs = cnt >> 1;
    const bool tail = (cnt & 1) != 0;

    int2 rwA = make_int2(0, 0), rwB = make_int2(0, 0);
    if (cnt > 0)    rwA = __ldg(g_prw + j0);
    if (npairs > 0) rwB = __ldg(g_prw + j0 + 1);

    int j = j0;
    for (int p = 0; p < npairs; ++p) {
        const ulonglong2 hvA = __ldg((const ulonglong2*)(h + (size_t)rwA.x * D + lane * 4));
        const ulonglong2 hvB = __ldg((const ulonglong2*)(h + (size_t)rwB.x * D + lane * 4));
        const float wA = __int_as_float(rwA.y);
        const float wB = __int_as_float(rwB.y);

        // uniform-address ea loads (all lanes same addr -> 1 wavefront, hot L1)
        float4 eaA[4], eaB[4];
#pragma unroll
        for (int g = 0; g < 4; ++g) {
            eaA[g] = __ldg((const float4*)(g_eas + (size_t)j * DE) + g);
            eaB[g] = __ldg((const float4*)(g_eas + (size_t)(j + 1) * DE) + g);
        }

        const int jn = j + 2;
        if (p + 1 < npairs) {
            rwA = __ldg(g_prw + jn);
            rwB = __ldg(g_prw + jn + 1);
        } else if (tail) {
            rwA = __ldg(g_prw + jn);
        }

        // two independent edge-MLP chains
        unsigned long long zA01 = b101, zA23 = b123, zB01 = b101, zB23 = b123;
#pragma unroll
        for (int k = 0; k < DE; ++k) {
            const float akA = ((const float*)eaA)[k];
            const float akB = ((const float*)eaB)[k];
            unsigned long long tA, tB;
            PACK2(tA, akA);
            PACK2(tB, akB);
            FMA2(zA01, tA, w101[k], zA01);
            FMA2(zB01, tB, w101[k], zB01);
            FMA2(zA23, tA, w123[k], zA23);
            FMA2(zB23, tB, w123[k], zB23);
        }
        {
            const float2 p01 = *(const float2*)&zA01, p23 = *(const float2*)&zA23;
            const float2 q01 = *(const float2*)&zB01, q23 = *(const float2*)&zB23;
            az0 += fmaxf(p01.x, 0.f) + fmaxf(q01.x, 0.f);
            az1 += fmaxf(p01.y, 0.f) + fmaxf(q01.y, 0.f);
            az2 += fmaxf(p23.x, 0.f) + fmaxf(q23.x, 0.f);
            az3 += fmaxf(p23.y, 0.f) + fmaxf(q23.y, 0.f);
        }
        unsigned long long wp;
        PACK2(wp, wA);
        FMA2(s01, wp, hvA.x, s01);
        FMA2(s23, wp, hvA.y, s23);
        PACK2(wp, wB);
        FMA2(s01, wp, hvB.x, s01);
        FMA2(s23, wp, hvB.y, s23);
        j = jn;
    }

    if (tail) {
        // metadata already in rwA (prefetched by last pair, or the cnt>0 init)
        const ulonglong2 hvA = __ldg((const ulonglong2*)(h + (size_t)rwA.x * D + lane * 4));
        const float wA = __int_as_float(rwA.y);
        float4 eaA[4];
#pragma unroll
        for (int g = 0; g < 4; ++g)
            eaA[g] = __ldg((const float4*)(g_eas + (size_t)j * DE) + g);

        unsigned long long zA01 = b101, zA23 = b123;
#pragma unroll
        for (int k = 0; k < DE; ++k) {
            const float ak = ((const float*)eaA)[k];
            unsigned long long tA; PACK2(tA, ak);
            FMA2(zA01, tA, w101[k], zA01);
            FMA2(zA23, tA, w123[k], zA23);
        }
        const float2 p01 = *(const float2*)&zA01, p23 = *(const float2*)&zA23;
        az0 += fmaxf(p01.x, 0.f);
        az1 += fmaxf(p01.y, 0.f);
        az2 += fmaxf(p23.x, 0.f);
        az3 += fmaxf(p23.y, 0.f);
        unsigned long long wp; PACK2(wp, wA);
        FMA2(s01, wp, hvA.x, s01);
        FMA2(s23, wp, hvA.y, s23);
    }

    ulonglong2 so; so.x = s01; so.y = s23;
    *(ulonglong2*)(g_S + (size_t)node * D + lane * 4) = so;
    *(float4*)(g_Z + (size_t)node * D + lane * 4) = make_float4(az0, az1, az2, az3);
}

// Fused: out = S @ lin_w + Z @ W2 + deg*b2 + bias ; LayerNorm ; relu  (f32x2 GEMM)
__global__ __launch_bounds__(512, 1) void k_node(
    const float* __restrict__ lw,
    const float* __restrict__ w2,
    const float* __restrict__ b2,
    const float* __restrict__ bias,
    const float* __restrict__ lnw,
    const float* __restrict__ lnb,
    float* __restrict__ dout,
    int layer)
{
    extern __shared__ __align__(16) float sm[];
    float* s_lw  = sm;
    float* s_w2  = sm + D * D;
    float* s_vec = sm + 2 * D * D;   // [b2 | bias | lnw | lnb]

    for (int i = threadIdx.x; i < D * D / 4; i += 512) {
        ((float4*)s_lw)[i] = ((const float4*)lw)[i];
        ((float4*)s_w2)[i] = ((const float4*)w2)[i];
    }
    if (threadIdx.x < D) {
        s_vec[threadIdx.x]         = b2[threadIdx.x];
        s_vec[D     + threadIdx.x] = bias[threadIdx.x];
        s_vec[2 * D + threadIdx.x] = lnw[threadIdx.x];
        s_vec[3 * D + threadIdx.x] = lnb[threadIdx.x];
    }
    __syncthreads();

    float* hout = (layer == 2) ? dout : g_h[layer & 1];
    const int lane = threadIdx.x & 31;
    const int wid  = threadIdx.x >> 5;
    const ulonglong2* lw2 = (const ulonglong2*)s_lw;
    const ulonglong2* w22 = (const ulonglong2*)s_w2;

    for (int tile = blockIdx.x * 64; tile < NN; tile += gridDim.x * 64) {
        const int r0 = tile + wid * 4;
        unsigned long long acc01[4], acc23[4];
#pragma unroll
        for (int i = 0; i < 4; ++i) { acc01[i] = 0ull; acc23[i] = 0ull; }

#pragma unroll 2
        for (int k = 0; k < D; k += 4) {
            float4 sv[4], zv[4];
#pragma unroll
            for (int i = 0; i < 4; ++i) {
                const int r = r0 + i;
                if (r < NN) {
                    sv[i] = __ldg((const float4*)(g_S + (size_t)r * D + k));
                    zv[i] = __ldg((const float4*)(g_Z + (size_t)r * D + k));
                } else {
                    sv[i] = make_float4(0.f, 0.f, 0.f, 0.f);
                    zv[i] = make_float4(0.f, 0.f, 0.f, 0.f);
                }
            }
#pragma unroll
            for (int kk = 0; kk < 4; ++kk) {
                const ulonglong2 wl = lw2[(k + kk) * 32 + lane];
                const ulonglong2 wv = w22[(k + kk) * 32 + lane];
#pragma unroll
                for (int i = 0; i < 4; ++i) {
                    const float sx = ((const float*)&sv[i])[kk];
                    const float zx = ((const float*)&zv[i])[kk];
                    unsigned long long sx2, zx2;
                    PACK2(sx2, sx);
                    PACK2(zx2, zx);
                    FMA2(acc01[i], sx2, wl.x, acc01[i]);
                    FMA2(acc01[i], zx2, wv.x, acc01[i]);
                    FMA2(acc23[i], sx2, wl.y, acc23[i]);
                    FMA2(acc23[i], zx2, wv.y, acc23[i]);
                }
            }
        }

        // Epilogue: +deg*b2 +bias, LayerNorm, relu, store
#pragma unroll
        for (int i = 0; i < 4; ++i) {
            const int r = r0 + i;
            if (r >= NN) continue;
            const float dg = (float)g_deg[r];
            const float2 a01 = *(const float2*)&acc01[i];
            const float2 a23 = *(const float2*)&acc23[i];
            float o[4] = { a01.x, a01.y, a23.x, a23.y };
#pragma unroll
            for (int jj = 0; jj < 4; ++jj) {
                const int c = lane * 4 + jj;
                o[jj] = o[jj] + dg * s_vec[c] + s_vec[D + c];
            }
            float sum = o[0] + o[1] + o[2] + o[3];
#pragma unroll
            for (int off = 16; off > 0; off >>= 1)
                sum += __shfl_xor_sync(0xffffffffu, sum, off);
            const float mu = sum * (1.f / D);
            float sq = 0.f;
#pragma unroll
            for (int jj = 0; jj < 4; ++jj) { const float dd = o[jj] - mu; sq = fmaf(dd, dd, sq); }
#pragma unroll
            for (int off = 16; off > 0; off >>= 1)
                sq += __shfl_xor_sync(0xffffffffu, sq, off);
            const float inv = rsqrtf(sq * (1.f / D) + 1e-5f);

            float4 res;
            float* rp = (float*)&res;
#pragma unroll
            for (int jj = 0; jj < 4; ++jj) {
                const int c = lane * 4 + jj;
                rp[jj] = fmaxf(fmaf((o[jj] - mu) * inv, s_vec[2 * D + c], s_vec[3 * D + c]), 0.f);
            }
            *(float4*)(hout + (size_t)r * D + lane * 4) = res;
        }
    }
}

extern "C" void kernel_launch(void* const* d_in, const int* in_sizes, int n_in,
                              void* d_out, int out_size)
{
    const float* x     = (const float*)d_in[0];
    const float* eattr = (const float*)d_in[1];
    const float* lin_w = (const float*)d_in[2];
    const float* ew1   = (const float*)d_in[3];
    const float* eb1   = (const float*)d_in[4];
    const float* ew2   = (const float*)d_in[5];
    const float* eb2   = (const float*)d_in[6];
    const float* bias  = (const float*)d_in[7];
    const float* lnw   = (const float*)d_in[8];
    const float* lnb   = (const float*)d_in[9];
    const int*   eidx  = (const int*)d_in[10];
    float* out = (float*)d_out;

    cudaFuncSetAttribute(k_node, cudaFuncAttributeMaxDynamicSharedMemorySize, NODE_SMEM);

    const int* erow = eidx;
    const int* ecol = eidx + EE;

    k_zero_deg<<<(NN + 1023) / 1024, 1024>>>();
    k_deg<<<(EE + 255) / 256, 256>>>(ecol);
    k_scan1<<<NSB, 1024>>>();
    k_scan2<<<1, 32>>>();
    k_fin<<<NSB, 1024>>>();
    k_perm<<<(EE + 255) / 256, 256>>>(erow, ecol, eattr);

    for (int l = 0; l < 3; ++l) {
        k_agg<<<(NN + 1) / 2, 64>>>(x, ew1 + l * DE * D, eb1 + l * D, l);
        k_node<<<152, 512, NODE_SMEM>>>(lin_w + l * D * D, ew2 + l * D * D,
                                        eb2 + l * D, bias + l * D,
                                        lnw + l * D, lnb + l * D, out, l);
    }
}

// round 10
// speedup vs baseline: 1.5077x; 1.4580x over previous
#include <cuda_runtime.h>
#include <cstdint>

#define NN 50000
#define EE 800000
#define D  128
#define DE 16
#define NSB 49           // scan blocks: ceil(50000/1024)

#define NODE_SMEM (2*D*D*4 + 4*D*4)

// Scratch (static __device__ arrays: no allocation allowed)
__device__ float g_h[2][NN * D];
__device__ float g_S[NN * D];
__device__ float g_Z[NN * D];
__device__ int   g_deg[NN];
__device__ float g_gn[NN];
__device__ int   g_off[NN + 1];
__device__ int   g_cur[NN];
__device__ int   g_pre[NN];                 // block-local exclusive prefix
__device__ int   g_bsum[64];                // per-block sums -> exclusive prefix
__device__ int2  g_prw[EE];                 // {row, bitcast(w)} dest-sorted
__device__ float g_eas[(size_t)EE * DE];    // edge_attr in dest-sorted order

#define PACK2(d, x)      asm("mov.b64 %0, {%1, %1};" : "=l"(d) : "f"(x))
#define FMA2(d, a, b, c) asm("fma.rn.f32x2 %0, %1, %2, %3;" : "=l"(d) : "l"(a), "l"(b), "l"(c))

__global__ void k_zero_deg() {
    int i = blockIdx.x * blockDim.x + threadIdx.x;
    if (i < NN) g_deg[i] = 0;
}

__global__ void k_deg(const int* __restrict__ col) {
    int e = blockIdx.x * blockDim.x + threadIdx.x;
    if (e < EE) atomicAdd(&g_deg[col[e]], 1);
}

// Pass 1: block-local exclusive scan of g_deg; write local prefix + block sum.
__global__ __launch_bounds__(1024) void k_scan1() {
    __shared__ int sw[32];
    const int t = threadIdx.x, lane = t & 31, wid = t >> 5;
    const int i = blockIdx.x * 1024 + t;
    const int v = (i < NN) ? g_deg[i] : 0;
    int x = v;
#pragma unroll
    for (int o = 1; o < 32; o <<= 1) {
        int y = __shfl_up_sync(0xffffffffu, x, o);
        if (lane >= o) x += y;
    }
    if (lane == 31) sw[wid] = x;
    __syncthreads();
    if (wid == 0) {
        int s = sw[lane];
#pragma unroll
        for (int o = 1; o < 32; o <<= 1) {
            int y = __shfl_up_sync(0xffffffffu, s, o);
            if (lane >= o) s += y;
        }
        sw[lane] = s;
    }
    __syncthreads();
    const int pre = (wid ? sw[wid - 1] : 0) + x - v;  // exclusive within block
    if (i < NN) g_pre[i] = pre;
    if (t == 1023) g_bsum[blockIdx.x] = pre + v;
}

// Pass 2: one warp scans the 49 block sums (exclusive).
__global__ void k_scan2() {
    const int lane = threadIdx.x;
    if (lane >= 32) return;
    int a = 0, b = 0;
    if (lane < NSB) a = g_bsum[lane];
    if (lane + 32 < NSB) b = g_bsum[lane + 32];
    const int a0 = a, b0 = b;
#pragma unroll
    for (int o = 1; o < 32; o <<= 1) {
        int y = __shfl_up_sync(0xffffffffu, a, o);
        if (lane >= o) a += y;
    }
    const int totA = __shfl_sync(0xffffffffu, a, 31);
#pragma unroll
    for (int o = 1; o < 32; o <<= 1) {
        int y = __shfl_up_sync(0xffffffffu, b, o);
        if (lane >= o) b += y;
    }
    if (lane < NSB) g_bsum[lane] = a - a0;
    if (lane + 32 < NSB) g_bsum[lane + 32] = totA + b - b0;
}

// Pass 3: finalize offsets, cursors, gcn-norm factors.
__global__ __launch_bounds__(1024) void k_fin() {
    const int i = blockIdx.x * 1024 + threadIdx.x;
    if (i < NN) {
        const int o = g_pre[i] + g_bsum[blockIdx.x];
        g_off[i] = o;
        g_cur[i] = o;
        const int d = g_deg[i];
        g_gn[i] = (d > 0) ? rsqrtf((float)d) : 0.f;
    }
    if (i == 0) g_off[NN] = EE;
}

// Counting-sort permute: edge e -> slot pos (sorted by destination col).
__global__ void k_perm(const int* __restrict__ row, const int* __restrict__ col,
                       const float* __restrict__ eattr) {
    int e = blockIdx.x * blockDim.x + threadIdx.x;
    if (e >= EE) return;
    const int c = col[e];
    const int r = row[e];
    const int pos = atomicAdd(&g_cur[c], 1);
    g_prw[pos] = make_int2(r, __float_as_int(g_gn[r] * g_gn[c]));
    const float4* src = (const float4*)(eattr + (size_t)e * DE);
    float4* dst = (float4*)(g_eas + (size_t)pos * DE);
    dst[0] = src[0]; dst[1] = src[1]; dst[2] = src[2]; dst[3] = src[3];
}

// Single-edge MLP + S update (inlined; independent chains get scheduled by ptxas)
__device__ __forceinline__ void edge_body(
    const unsigned long long* w101, const unsigned long long* w123,
    unsigned long long b101, unsigned long long b123,
    float a, float w, const ulonglong2& hv,
    unsigned long long& s01, unsigned long long& s23,
    float& az0, float& az1, float& az2, float& az3)
{
    unsigned long long z01 = b101, z23 = b123;
#pragma unroll
    for (int k = 0; k < DE; ++k) {
        const float ak = __shfl_sync(0xffffffffu, a, k);
        unsigned long long ak2; PACK2(ak2, ak);
        FMA2(z01, ak2, w101[k], z01);
        FMA2(z23, ak2, w123[k], z23);
    }
    const float2 zl = *(const float2*)&z01;
    const float2 zh = *(const float2*)&z23;
    az0 += fmaxf(zl.x, 0.f); az1 += fmaxf(zl.y, 0.f);
    az2 += fmaxf(zh.x, 0.f); az3 += fmaxf(zh.y, 0.f);
    unsigned long long wp; PACK2(wp, w);
    FMA2(s01, wp, hv.x, s01);
    FMA2(s23, wp, hv.y, s23);
}

// One warp per destination node. 3-stage pipeline: metadata 2 pairs ahead,
// h gathers 1 pair ahead (full L2-latency cover). 128-thr blocks, 3 blocks/SM.
__global__ __launch_bounds__(128, 3) void k_agg(
    const float* __restrict__ x,
    const float* __restrict__ w1,
    const float* __restrict__ b1,
    int layer)
{
    const float* __restrict__ h = (layer == 0) ? x : g_h[(layer - 1) & 1];
    const int lane = threadIdx.x & 31;

    // W1 columns for this lane in registers as f32x2 pairs
    unsigned long long w101[DE], w123[DE], b101, b123;
    {
        const ulonglong2 bv = *(const ulonglong2*)(b1 + lane * 4);
        b101 = bv.x; b123 = bv.y;
#pragma unroll
        for (int k = 0; k < DE; ++k) {
            const ulonglong2 wv = *(const ulonglong2*)(w1 + k * D + lane * 4);
            w101[k] = wv.x; w123[k] = wv.y;
        }
    }

    const int node = blockIdx.x * 4 + (threadIdx.x >> 5);
    if (node >= NN) return;
    const int j0 = g_off[node], j1 = g_off[node + 1];
    const int cnt = j1 - j0;

    unsigned long long s01 = 0ull, s23 = 0ull;
    float az0 = 0.f, az1 = 0.f, az2 = 0.f, az3 = 0.f;

    const int P = cnt >> 1;
    const bool tail = (cnt & 1) != 0;

    if (P >= 2) {
        // stage 0: metadata for pairs 0 and 1
        int2 rwA0 = __ldg(g_prw + j0);
        int2 rwB0 = __ldg(g_prw + j0 + 1);
        float aA0 = (lane < DE) ? __ldg(g_eas + (size_t)j0 * DE + lane) : 0.f;
        float aB0 = (lane < DE) ? __ldg(g_eas + (size_t)(j0 + 1) * DE + lane) : 0.f;
        int2 rwA1 = __ldg(g_prw + j0 + 2);
        int2 rwB1 = __ldg(g_prw + j0 + 3);
        float aA1 = (lane < DE) ? __ldg(g_eas + (size_t)(j0 + 2) * DE + lane) : 0.f;
        float aB1 = (lane < DE) ? __ldg(g_eas + (size_t)(j0 + 3) * DE + lane) : 0.f;
        // h for pair 0
        ulonglong2 hvA = __ldg((const ulonglong2*)(h + (size_t)rwA0.x * D + lane * 4));
        ulonglong2 hvB = __ldg((const ulonglong2*)(h + (size_t)rwB0.x * D + lane * 4));

        for (int p = 0; p < P; ++p) {
            // issue h gathers for the next pair / tail (addresses resident)
            ulonglong2 hvA_n = hvA, hvB_n = hvB;
            if (p + 1 < P) {
                hvA_n = __ldg((const ulonglong2*)(h + (size_t)rwA1.x * D + lane * 4));
                hvB_n = __ldg((const ulonglong2*)(h + (size_t)rwB1.x * D + lane * 4));
            } else if (tail) {
                hvA_n = __ldg((const ulonglong2*)(h + (size_t)rwA1.x * D + lane * 4));
            }
            // load metadata 2 pairs ahead (or the tail edge)
            int2 rwA2 = rwA1, rwB2 = rwB1;
            float aA2 = aA1, aB2 = aB1;
            const int jf = j0 + 2 * (p + 2);
            if (p + 2 < P) {
                rwA2 = __ldg(g_prw + jf);
                rwB2 = __ldg(g_prw + jf + 1);
                aA2 = (lane < DE) ? __ldg(g_eas + (size_t)jf * DE + lane) : 0.f;
                aB2 = (lane < DE) ? __ldg(g_eas + (size_t)(jf + 1) * DE + lane) : 0.f;
            } else if (p + 2 == P && tail) {
                rwA2 = __ldg(g_prw + jf);
                aA2 = (lane < DE) ? __ldg(g_eas + (size_t)jf * DE + lane) : 0.f;
            }
            // compute pair p
            edge_body(w101, w123, b101, b123, aA0, __int_as_float(rwA0.y), hvA,
                      s01, s23, az0, az1, az2, az3);
            edge_body(w101, w123, b101, b123, aB0, __int_as_float(rwB0.y), hvB,
                      s01, s23, az0, az1, az2, az3);
            // rotate pipeline
            rwA0 = rwA1; rwB0 = rwB1; aA0 = aA1; aB0 = aB1;
            rwA1 = rwA2; rwB1 = rwB2; aA1 = aA2; aB1 = aB2;
            hvA = hvA_n; hvB = hvB_n;
        }
        if (tail) {
            // after rotation: rwA0/aA0 hold tail metadata, hvA its h row
            edge_body(w101, w123, b101, b123, aA0, __int_as_float(rwA0.y), hvA,
                      s01, s23, az0, az1, az2, az3);
        }
    } else {
        // rare path: cnt in 0..3, simple serial loop
        for (int j = j0; j < j1; ++j) {
            const int2 rw = __ldg(g_prw + j);
            const float a = (lane < DE) ? __ldg(g_eas + (size_t)j * DE + lane) : 0.f;
            const ulonglong2 hv = __ldg((const ulonglong2*)(h + (size_t)rw.x * D + lane * 4));
            edge_body(w101, w123, b101, b123, a, __int_as_float(rw.y), hv,
                      s01, s23, az0, az1, az2, az3);
        }
    }

    ulonglong2 so; so.x = s01; so.y = s23;
    *(ulonglong2*)(g_S + (size_t)node * D + lane * 4) = so;
    *(float4*)(g_Z + (size_t)node * D + lane * 4) = make_float4(az0, az1, az2, az3);
}

// Fused: out = S @ lin_w + Z @ W2 + deg*b2 + bias ; LayerNorm ; relu  (f32x2 GEMM)
__global__ __launch_bounds__(512, 1) void k_node(
    const float* __restrict__ lw,
    const float* __restrict__ w2,
    const float* __restrict__ b2,
    const float* __restrict__ bias,
    const float* __restrict__ lnw,
    const float* __restrict__ lnb,
    float* __restrict__ dout,
    int layer)
{
    extern __shared__ __align__(16) float sm[];
    float* s_lw  = sm;
    float* s_w2  = sm + D * D;
    float* s_vec = sm + 2 * D * D;   // [b2 | bias | lnw | lnb]

    for (int i = threadIdx.x; i < D * D / 4; i += 512) {
        ((float4*)s_lw)[i] = ((const float4*)lw)[i];
        ((float4*)s_w2)[i] = ((const float4*)w2)[i];
    }
    if (threadIdx.x < D) {
        s_vec[threadIdx.x]         = b2[threadIdx.x];
        s_vec[D     + threadIdx.x] = bias[threadIdx.x];
        s_vec[2 * D + threadIdx.x] = lnw[threadIdx.x];
        s_vec[3 * D + threadIdx.x] = lnb[threadIdx.x];
    }
    __syncthreads();

    float* hout = (layer == 2) ? dout : g_h[layer & 1];
    const int lane = threadIdx.x & 31;
    const int wid  = threadIdx.x >> 5;
    const ulonglong2* lw2 = (const ulonglong2*)s_lw;
    const ulonglong2* w22 = (const ulonglong2*)s_w2;

    for (int tile = blockIdx.x * 64; tile < NN; tile += gridDim.x * 64) {
        const int r0 = tile + wid * 4;
        unsigned long long acc01[4], acc23[4];
#pragma unroll
        for (int i = 0; i < 4; ++i) { acc01[i] = 0ull; acc23[i] = 0ull; }

#pragma unroll 2
        for (int k = 0; k < D; k += 4) {
            float4 sv[4], zv[4];
#pragma unroll
            for (int i = 0; i < 4; ++i) {
                const int r = r0 + i;
                if (r < NN) {
                    sv[i] = __ldg((const float4*)(g_S + (size_t)r * D + k));
                    zv[i] = __ldg((const float4*)(g_Z + (size_t)r * D + k));
                } else {
                    sv[i] = make_float4(0.f, 0.f, 0.f, 0.f);
                    zv[i] = make_float4(0.f, 0.f, 0.f, 0.f);
                }
            }
#pragma unroll
            for (int kk = 0; kk < 4; ++kk) {
                const ulonglong2 wl = lw2[(k + kk) * 32 + lane];
                const ulonglong2 wv = w22[(k + kk) * 32 + lane];
#pragma unroll
                for (int i = 0; i < 4; ++i) {
                    const float sx = ((const float*)&sv[i])[kk];
                    const float zx = ((const float*)&zv[i])[kk];
                    unsigned long long sx2, zx2;
                    PACK2(sx2, sx);
                    PACK2(zx2, zx);
                    FMA2(acc01[i], sx2, wl.x, acc01[i]);
                    FMA2(acc01[i], zx2, wv.x, acc01[i]);
                    FMA2(acc23[i], sx2, wl.y, acc23[i]);
                    FMA2(acc23[i], zx2, wv.y, acc23[i]);
                }
            }
        }

        // Epilogue: +deg*b2 +bias, LayerNorm, relu, store
#pragma unroll
        for (int i = 0; i < 4; ++i) {
            const int r = r0 + i;
            if (r >= NN) continue;
            const float dg = (float)g_deg[r];
            const float2 a01 = *(const float2*)&acc01[i];
            const float2 a23 = *(const float2*)&acc23[i];
            float o[4] = { a01.x, a01.y, a23.x, a23.y };
#pragma unroll
            for (int jj = 0; jj < 4; ++jj) {
                const int c = lane * 4 + jj;
                o[jj] = o[jj] + dg * s_vec[c] + s_vec[D + c];
            }
            float sum = o[0] + o[1] + o[2] + o[3];
#pragma unroll
            for (int off = 16; off > 0; off >>= 1)
                sum += __shfl_xor_sync(0xffffffffu, sum, off);
            const float mu = sum * (1.f / D);
            float sq = 0.f;
#pragma unroll
            for (int jj = 0; jj < 4; ++jj) { const float dd = o[jj] - mu; sq = fmaf(dd, dd, sq); }
#pragma unroll
            for (int off = 16; off > 0; off >>= 1)
                sq += __shfl_xor_sync(0xffffffffu, sq, off);
            const float inv = rsqrtf(sq * (1.f / D) + 1e-5f);

            float4 res;
            float* rp = (float*)&res;
#pragma unroll
            for (int jj = 0; jj < 4; ++jj) {
                const int c = lane * 4 + jj;
                rp[jj] = fmaxf(fmaf((o[jj] - mu) * inv, s_vec[2 * D + c], s_vec[3 * D + c]), 0.f);
            }
            *(float4*)(hout + (size_t)r * D + lane * 4) = res;
        }
    }
}

extern "C" void kernel_launch(void* const* d_in, const int* in_sizes, int n_in,
                              void* d_out, int out_size)
{
    const float* x     = (const float*)d_in[0];
    const float* eattr = (const float*)d_in[1];
    const float* lin_w = (const float*)d_in[2];
    const float* ew1   = (const float*)d_in[3];
    const float* eb1   = (const float*)d_in[4];
    const float* ew2   = (const float*)d_in[5];
    const float* eb2   = (const float*)d_in[6];
    const float* bias  = (const float*)d_in[7];
    const float* lnw   = (const float*)d_in[8];
    const float* lnb   = (const float*)d_in[9];
    const int*   eidx  = (const int*)d_in[10];
    float* out = (float*)d_out;

    cudaFuncSetAttribute(k_node, cudaFuncAttributeMaxDynamicSharedMemorySize, NODE_SMEM);

    const int* erow = eidx;
    const int* ecol = eidx + EE;

    k_zero_deg<<<(NN + 1023) / 1024, 1024>>>();
    k_deg<<<(EE + 255) / 256, 256>>>(ecol);
    k_scan1<<<NSB, 1024>>>();
    k_scan2<<<1, 32>>>();
    k_fin<<<NSB, 1024>>>();
    k_perm<<<(EE + 255) / 256, 256>>>(erow, ecol, eattr);

    for (int l = 0; l < 3; ++l) {
        k_agg<<<(NN + 3) / 4, 128>>>(x, ew1 + l * DE * D, eb1 + l * D, l);
        k_node<<<152, 512, NODE_SMEM>>>(lin_w + l * D * D, ew2 + l * D * D,
                                        eb2 + l * D, bias + l * D,
                                        lnw + l * D, lnb + l * D, out, l);
    }
}